// round 13
// baseline (speedup 1.0000x reference)
#include <cuda_runtime.h>
#include <math.h>

// Hyperbolic conv constants (must match reference)
#define CC    0.05f
#define SQC   0.22360679774997896f          // sqrt(0.05)
#define MINN  1e-15f
#define MAXN  (0.996f / SQC)                // (1 - 4e-3)/sqrt(c)
#define MAXN2 (MAXN * MAXN)

typedef unsigned long long u64;

// u tile stride padded to 68 floats (272B = 17*16B) so every row is 16B aligned
#define TW    68
#define TSZ   (66 * TW)                     // 4488 floats per tile
#define TSZ4  (TSZ / 4)                     // 1122 float4

// Scratch: u = logmap0(pad(x)), [b][j][66*68], 32*64*4488 floats (~36.8MB)
__device__ float g_u[9191424];
__device__ float g_bh[128];                 // expmap0(bias)

// ---------------------------------------------------------------------------
// packed f32x2 + fast-approx + cp.async helpers
// ---------------------------------------------------------------------------
__device__ __forceinline__ u64 pk(float a, float b) {
    u64 r;
    asm("mov.b64 %0, {%1, %2};" : "=l"(r)
        : "r"(__float_as_uint(a)), "r"(__float_as_uint(b)));
    return r;
}
__device__ __forceinline__ float2 unpk(u64 v) {
    unsigned lo, hi;
    asm("mov.b64 {%0, %1}, %2;" : "=r"(lo), "=r"(hi) : "l"(v));
    return make_float2(__uint_as_float(lo), __uint_as_float(hi));
}
__device__ __forceinline__ u64 fma2(u64 a, u64 b, u64 c) {
    u64 d;
    asm("fma.rn.f32x2 %0, %1, %2, %3;" : "=l"(d) : "l"(a), "l"(b), "l"(c));
    return d;
}
__device__ __forceinline__ float fexp2(float x){ float r; asm("ex2.approx.f32 %0, %1;" : "=f"(r) : "f"(x)); return r; }
__device__ __forceinline__ float frcp (float x){ float r; asm("rcp.approx.f32 %0, %1;" : "=f"(r) : "f"(x)); return r; }
__device__ __forceinline__ float frsq (float x){ float r; asm("rsqrt.approx.f32 %0, %1;" : "=f"(r) : "f"(x)); return r; }

__device__ __forceinline__ void cpasync16(unsigned saddr, const void* g) {
    asm volatile("cp.async.cg.shared.global [%0], [%1], 16;" :: "r"(saddr), "l"(g));
}
#define CP_COMMIT() asm volatile("cp.async.commit_group;")
#define CP_WAIT0()  asm volatile("cp.async.wait_group 0;")

__device__ __forceinline__ float4 add4(float4 a, float4 b) {
    return make_float4(a.x + b.x, a.y + b.y, a.z + b.z, a.w + b.w);
}

__device__ __forceinline__ float artanhc(float z) {
    z = fminf(z, 1.0f - 1e-7f);             // z >= 0 always here
    return 0.5f * (log1pf(z) - log1pf(-z));
}

// ---------------------------------------------------------------------------
// Kernel 1: u = logmap0(pad(x)) per (b, cin) row (precise), stride-68 layout.
// Block 2048 additionally computes b_h = expmap0(bias).
// ---------------------------------------------------------------------------
__global__ __launch_bounds__(256) void u_kernel(const float* __restrict__ x,
                                                const float* __restrict__ bias) {
    int row = blockIdx.x;
    int t = threadIdx.x;

    if (row == 2048) {                      // bias block
        if (t < 128) {
            float v = bias[t];
            float p = v * v;
            #pragma unroll
            for (int o = 16; o > 0; o >>= 1) p += __shfl_xor_sync(0xffffffffu, p, o);
            __shared__ float smb[4];
            if ((t & 31) == 0) smb[t >> 5] = p;
            __syncwarp();
            asm volatile("bar.sync 1, 128;");
            float s2 = smb[0] + smb[1] + smb[2] + smb[3];
            float bn = fmaxf(sqrtf(s2), MINN);
            float z  = SQC * bn;
            g_bh[t] = tanhf(z) / z * v;
        }
        return;
    }

    const float* xr = x + (size_t)row * 4096;

    float p = 0.0f;
    #pragma unroll
    for (int k = 0; k < 16; k++) { float v = xr[t + (k << 8)]; p += v * v; }
    #pragma unroll
    for (int o = 16; o > 0; o >>= 1) p += __shfl_xor_sync(0xffffffffu, p, o);
    __shared__ float sm[8];
    __shared__ float s_scale;
    if ((t & 31) == 0) sm[t >> 5] = p;
    __syncthreads();
    if (t == 0) {
        float s2 = 0.0f;
        #pragma unroll
        for (int i = 0; i < 8; i++) s2 += sm[i];
        float yn = fmaxf(sqrtf(s2), MINN);
        float z  = SQC * yn;
        s_scale  = artanhc(z) / z;
    }
    __syncthreads();
    float sc = s_scale;

    float* ur = g_u + (size_t)row * TSZ;
    for (int idx = t; idx < TSZ; idx += 256) {
        int r = idx / TW, c = idx - r * TW;
        float v = 0.0f;
        if (r >= 1 && r <= 64 && c >= 1 && c <= 64)
            v = xr[(r - 1) * 64 + (c - 1)] * sc;
        ur[idx] = v;
    }
}

// ---------------------------------------------------------------------------
// Mobius scan scalar math — short chain (no sqrt on common path).
// acc = P*q;  qv = <q,v>.  Returns (sA, sBt); updates a2 = |acc'|^2.
// ---------------------------------------------------------------------------
__device__ __forceinline__ float2 step_scalars(float sv2, float qv, float P, float& a2) {
    float z2 = CC * sv2;                           // z^2
    float tau;
    if (z2 < 0.0625f) {                            // z < 0.25 (always, this data)
        tau = 1.0f + z2 * (-0.33333334f + z2 * (0.13333334f - z2 * 0.053968254f));
    } else {
        float vn = sv2 * frsq(fmaxf(sv2, 1e-28f));
        float z  = SQC * vn;
        float t  = fexp2(z * 2.8853901f);          // e^{2z}
        tau = (t - 1.0f) * frcp((t + 1.0f) * z);
    }
    float tn2 = tau * tau * sv2;                   // |t|^2 before project
    float ts  = tau;
    if (tn2 > MAXN2) ts = tau * (MAXN * frsq(tn2));  // project(t), rare
    float y2  = ts * ts * sv2;
    float xy  = ts * (P * qv);
    float x2  = a2;
    float A   = 1.0f + 2.0f * CC * xy + CC * y2;
    float B   = 1.0f - CC * x2;
    float den = fmaxf(1.0f + 2.0f * CC * xy + CC * CC * x2 * y2, MINN);
    float inv = frcp(den);
    float n2  = (A * A * x2 + 2.0f * A * B * xy + B * B * y2) * (inv * inv);
    float ps  = 1.0f;
    if (n2 > MAXN2) ps = MAXN * frsq(fmaxf(n2, 1e-28f));  // project(acc'), rare
    a2 = ps * ps * n2;
    return make_float2(A * inv * ps, B * inv * ps * ts);
}

__device__ __forceinline__ float2 final_scalars(float sacc, float a2, float bh) {
    float y2  = 4096.0f * bh * bh;
    float xy  = bh * sacc;
    float x2  = a2;
    float A   = 1.0f + 2.0f * CC * xy + CC * y2;
    float B   = 1.0f - CC * x2;
    float den = fmaxf(1.0f + 2.0f * CC * xy + CC * CC * x2 * y2, MINN);
    float inv = frcp(den);
    float n2  = (A * A * x2 + 2.0f * A * B * xy + B * B * y2) * (inv * inv);
    float ps  = 1.0f;
    if (n2 > MAXN2) ps = MAXN * frsq(fmaxf(n2, 1e-28f));
    return make_float2(A * inv * ps, B * inv * ps * bh);
}

// load one 6-wide window row (16B-aligned) as 5 overlapping f32x2 pairs
__device__ __forceinline__ void loadrow(const float* p, u64* row) {
    float4 a = *(const float4*)p;           // floats 0-3 (LDS.128)
    float2 b = *(const float2*)(p + 4);     // floats 4-5 (LDS.64)
    row[0] = pk(a.x, a.y);
    row[1] = pk(a.y, a.z);
    row[2] = pk(a.z, a.w);
    row[3] = pk(a.w, b.x);
    row[4] = pk(b.x, b.y);
}

// ---------------------------------------------------------------------------
// Kernel 2: one CTA per (b, channel pair) — the R11 configuration (best),
// plus a 6-SHFL 4-value reduce-scatter butterfly.
// 256 threads, 4x4 outputs each, columns packed f32x2. cp.async double
// buffer, one barrier per scan step, lane-parity dual Mobius chains.
// ---------------------------------------------------------------------------
__global__ __launch_bounds__(256, 2)
void main_kernel(const float* __restrict__ w, float* __restrict__ out) {
    const int b    = blockIdx.y;
    const int c0   = blockIdx.x * 2;
    const int tid  = threadIdx.x;
    const int ty   = tid >> 4;
    const int tx   = tid & 15;
    const int lane = tid & 31;
    const int wid  = tid >> 5;
    const int par  = lane & 1;          // my scalar-chain channel (0 or 1)

    __shared__ float  su[2 * TSZ];      // double-buffered 66x68 tile
    __shared__ u64    swp[2][576];      // weights pre-duplicated (w,w)
    __shared__ float4 sred[2][8];       // [buf][warp] -> (s0,s1,d0,d1)
    __shared__ float2 sepi[8];

    for (int i = tid; i < 1152; i += 256) {
        int cc = i / 576, rem = i - cc * 576;
        float wv = w[(size_t)(c0 + cc) * 576 + rem];
        swp[cc][rem] = pk(wv, wv);
    }

    const unsigned su_s = (unsigned)__cvta_generic_to_shared(su);
    const float4* gbase = (const float4*)(g_u + (size_t)(b * 64) * TSZ);
    const int tail = tid + 1024;            // only first 98 threads copy chunk 5

    // preload tile 0 into buf0 via cp.async
    #pragma unroll
    for (int k = 0; k < 4; k++) {
        int i = tid + (k << 8);
        cpasync16(su_s + i * 16, gbase + i);
    }
    if (tail < TSZ4) cpasync16(su_s + tail * 16, gbase + tail);
    CP_COMMIT();
    CP_WAIT0();
    __syncthreads();

    u64 q0a[8], q1a[8];                 // acc = P * q, packed col pairs
    #pragma unroll
    for (int i = 0; i < 8; i++) { q0a[i] = 0ull; q1a[i] = 0ull; }
    float a2m = 0.0f, Pm = 1.0f;        // per-lane: channel `par`'s scan state

    const int baseoff = (4 * ty) * TW + 4 * tx;

    #pragma unroll 2
    for (int j = 0; j < 64; j++) {
        const int cur = j & 1;

        // ---- branchless async prefetch of tile (j+1)&63 into other buffer ----
        {
            const float4* gn = gbase + (size_t)((j + 1) & 63) * TSZ4;
            unsigned sn = su_s + (cur ^ 1) * (TSZ * 4);
            #pragma unroll
            for (int k = 0; k < 4; k++) {
                int i = tid + (k << 8);
                cpasync16(sn + i * 16, gn + i);
            }
            if (tail < TSZ4) cpasync16(sn + tail * 16, gn + tail);
            CP_COMMIT();
        }

        const float* basep = su + cur * TSZ + baseoff;
        const u64* wp0 = &swp[0][j * 9];
        const u64* wp1 = &swp[1][j * 9];

        // ---- conv: rolling 3-row window; weights broadcast from smem ----
        u64 v0[8], v1[8];
        u64 rwin[3][5];
        #pragma unroll
        for (int r = 0; r < 3; r++) loadrow(basep + r * TW, rwin[r]);

        #pragma unroll
        for (int orow = 0; orow < 4; orow++) {
            u64 s00 = 0ull, s01 = 0ull, s10 = 0ull, s11 = 0ull;
            #pragma unroll
            for (int r = 0; r < 3; r++) {
                const u64* rw = rwin[(orow + r) % 3];
                #pragma unroll
                for (int k = 0; k < 3; k++) {
                    u64 wa = wp0[r * 3 + k];
                    u64 wb = wp1[r * 3 + k];
                    s00 = fma2(rw[k],     wa, s00);
                    s01 = fma2(rw[2 + k], wa, s01);
                    s10 = fma2(rw[k],     wb, s10);
                    s11 = fma2(rw[2 + k], wb, s11);
                }
            }
            v0[orow * 2]     = s00;
            v0[orow * 2 + 1] = s01;
            v1[orow * 2]     = s10;
            v1[orow * 2 + 1] = s11;
            if (orow < 3) loadrow(basep + (orow + 3) * TW, rwin[orow % 3]);
        }

        // ---- fused packed reduction: |v|^2 and <q,v> per channel ----
        u64 sq0 = 0ull, av0 = 0ull, sq1 = 0ull, av1 = 0ull;
        #pragma unroll
        for (int i = 0; i < 8; i++) {
            sq0 = fma2(v0[i], v0[i], sq0);
            av0 = fma2(q0a[i], v0[i], av0);
            sq1 = fma2(v1[i], v1[i], sq1);
            av1 = fma2(q1a[i], v1[i], av1);
        }
        float2 pa = unpk(sq0), pb = unpk(av0), pc = unpk(sq1), pd = unpk(av1);
        float t0 = pa.x + pa.y;               // s0: |v0|^2 partial
        float t1 = pc.x + pc.y;               // s1: |v1|^2 partial
        float t2 = pb.x + pb.y;               // d0: <q0,v0> partial
        float t3 = pd.x + pd.y;               // d1: <q1,v1> partial

        // ---- 4-value reduce-scatter butterfly (6 SHFL total) ----
        // stage 1 (xor 1): value bit0
        float kA = (lane & 1) ? t1 : t0;
        float sA = (lane & 1) ? t0 : t1;
        float kB = (lane & 1) ? t3 : t2;
        float sB = (lane & 1) ? t2 : t3;
        kA += __shfl_xor_sync(0xffffffffu, sA, 1);
        kB += __shfl_xor_sync(0xffffffffu, sB, 1);
        // stage 2 (xor 2): value bit1
        float kC = (lane & 2) ? kB : kA;
        float sC = (lane & 2) ? kA : kB;
        kC += __shfl_xor_sync(0xffffffffu, sC, 2);
        // full butterfly over remaining distances
        #pragma unroll
        for (int o = 4; o <= 16; o <<= 1)
            kC += __shfl_xor_sync(0xffffffffu, kC, o);
        // lane holds warp total of value idx = lane&3: 0=s0,1=s1,2=d0,3=d1
        if (lane < 4) ((float*)&sred[cur][wid])[lane] = kC;

        // prefetch must land before the barrier publishes the buffer
        CP_WAIT0();
        __syncthreads();                      // single barrier per scan step

        // tree-sum the 8 warp float4 partials
        float4 u01 = add4(sred[cur][0], sred[cur][1]);
        float4 u23 = add4(sred[cur][2], sred[cur][3]);
        float4 u45 = add4(sred[cur][4], sred[cur][5]);
        float4 u67 = add4(sred[cur][6], sred[cur][7]);
        float4 tt  = add4(add4(u01, u23), add4(u45, u67));
        // tt = (s0, s1, d0, d1)

        // ---- lane-parity scalar chain: even lanes ch0, odd lanes ch1 ----
        float sv2 = par ? tt.y : tt.x;
        float qv  = par ? tt.w : tt.z;
        float2 s = step_scalars(sv2, qv, Pm, a2m);
        Pm *= s.x;
        float qcm = s.y * frcp(Pm);
        float qc0 = __shfl_sync(0xffffffffu, qcm, 0);
        float qc1 = __shfl_sync(0xffffffffu, qcm, 1);
        u64 QC0 = pk(qc0, qc0), QC1 = pk(qc1, qc1);
        #pragma unroll
        for (int i = 0; i < 8; i++) {
            q0a[i] = fma2(QC0, v0[i], q0a[i]);
            q1a[i] = fma2(QC1, v1[i], q1a[i]);
        }
    }

    // ---- epilogue: mobius bias add + project (acc = P*q) ----
    float sa0 = 0.0f, sa1 = 0.0f;
    #pragma unroll
    for (int i = 0; i < 8; i++) {
        float2 p0 = unpk(q0a[i]); sa0 += p0.x + p0.y;
        float2 p1 = unpk(q1a[i]); sa1 += p1.x + p1.y;
    }
    {
        float m  = par ? sa1 : sa0;
        float ot = par ? sa0 : sa1;
        m += __shfl_xor_sync(0xffffffffu, ot, 1);
        #pragma unroll
        for (int o = 2; o <= 16; o <<= 1)
            m += __shfl_xor_sync(0xffffffffu, m, o);
        if (lane < 2) ((float*)&sepi[wid])[par] = m;
    }
    __syncthreads();
    float tm = 0.0f;
    #pragma unroll
    for (int i = 0; i < 8; i++) tm += ((float*)&sepi[i])[par];

    // lane-parity final scalars, then broadcast
    float2 f = final_scalars(Pm * tm, a2m, g_bh[c0 + par]);
    float fxm = f.x * Pm;
    float fa0 = __shfl_sync(0xffffffffu, fxm, 0);
    float fb0 = __shfl_sync(0xffffffffu, f.y, 0);
    float fa1 = __shfl_sync(0xffffffffu, fxm, 1);
    float fb1 = __shfl_sync(0xffffffffu, f.y, 1);
    u64 FA0 = pk(fa0, fa0), FB0 = pk(fb0, fb0);
    u64 FA1 = pk(fa1, fa1), FB1 = pk(fb1, fb1);

    u64* o0 = (u64*)(out + ((size_t)(b * 128 + c0)) * 4096);
    u64* o1 = o0 + 2048;
    #pragma unroll
    for (int orow = 0; orow < 4; orow++) {
        #pragma unroll
        for (int p = 0; p < 2; p++) {
            int pos = (4 * ty + orow) * 32 + 2 * tx + p;   // in float2 units
            o0[pos] = fma2(FA0, q0a[orow * 2 + p], FB0);
            o1[pos] = fma2(FA1, q1a[orow * 2 + p], FB1);
        }
    }
}

// ---------------------------------------------------------------------------
extern "C" void kernel_launch(void* const* d_in, const int* in_sizes, int n_in,
                              void* d_out, int out_size) {
    const float* x    = (const float*)d_in[0];   // [32,64,64,64]
    const float* wgt  = (const float*)d_in[1];   // [128,64,3,3]
    const float* bias = (const float*)d_in[2];   // [128]
    float* out = (float*)d_out;                  // [32,128,64,64]

    u_kernel<<<2049, 256>>>(x, bias);            // block 2048 also does bias
    dim3 grid(64, 32);                           // (cout/2, bs)
    main_kernel<<<grid, 256>>>(wgt, out);
}

// round 14
// speedup vs baseline: 1.1022x; 1.1022x over previous
#include <cuda_runtime.h>
#include <math.h>

// Hyperbolic conv constants (must match reference)
#define CC    0.05f
#define SQC   0.22360679774997896f          // sqrt(0.05)
#define MINN  1e-15f
#define MAXN  (0.996f / SQC)                // (1 - 4e-3)/sqrt(c)
#define MAXN2 (MAXN * MAXN)

typedef unsigned long long u64;

// u tile stride padded to 68 floats (272B = 17*16B) so every row is 16B aligned
#define TW    68
#define TSZ   (66 * TW)                     // 4488 floats per tile
#define TSZ4  (TSZ / 4)                     // 1122 float4

// Scratch: u = logmap0(pad(x)), [b][j][66*68], 32*64*4488 floats (~36.8MB)
__device__ float g_u[9191424];
__device__ float g_bh[128];                 // expmap0(bias)

// ---------------------------------------------------------------------------
// packed f32x2 + fast-approx + cp.async helpers
// ---------------------------------------------------------------------------
__device__ __forceinline__ u64 pk(float a, float b) {
    u64 r;
    asm("mov.b64 %0, {%1, %2};" : "=l"(r)
        : "r"(__float_as_uint(a)), "r"(__float_as_uint(b)));
    return r;
}
__device__ __forceinline__ float2 unpk(u64 v) {
    unsigned lo, hi;
    asm("mov.b64 {%0, %1}, %2;" : "=r"(lo), "=r"(hi) : "l"(v));
    return make_float2(__uint_as_float(lo), __uint_as_float(hi));
}
__device__ __forceinline__ u64 fma2(u64 a, u64 b, u64 c) {
    u64 d;
    asm("fma.rn.f32x2 %0, %1, %2, %3;" : "=l"(d) : "l"(a), "l"(b), "l"(c));
    return d;
}
__device__ __forceinline__ float fexp2(float x){ float r; asm("ex2.approx.f32 %0, %1;" : "=f"(r) : "f"(x)); return r; }
__device__ __forceinline__ float frcp (float x){ float r; asm("rcp.approx.f32 %0, %1;" : "=f"(r) : "f"(x)); return r; }
__device__ __forceinline__ float frsq (float x){ float r; asm("rsqrt.approx.f32 %0, %1;" : "=f"(r) : "f"(x)); return r; }

__device__ __forceinline__ void cpasync16(unsigned saddr, const void* g) {
    asm volatile("cp.async.cg.shared.global [%0], [%1], 16;" :: "r"(saddr), "l"(g));
}
#define CP_COMMIT() asm volatile("cp.async.commit_group;")
#define CP_WAIT0()  asm volatile("cp.async.wait_group 0;")

__device__ __forceinline__ float artanhc(float z) {
    z = fminf(z, 1.0f - 1e-7f);             // z >= 0 always here
    return 0.5f * (log1pf(z) - log1pf(-z));
}

// ---------------------------------------------------------------------------
// Kernel 1: u = logmap0(pad(x)) per (b, cin) row (precise), stride-68 layout.
// Block 2048 additionally computes b_h = expmap0(bias).
// ---------------------------------------------------------------------------
__global__ __launch_bounds__(256) void u_kernel(const float* __restrict__ x,
                                                const float* __restrict__ bias) {
    int row = blockIdx.x;
    int t = threadIdx.x;

    if (row == 2048) {                      // bias block
        if (t < 128) {
            float v = bias[t];
            float p = v * v;
            #pragma unroll
            for (int o = 16; o > 0; o >>= 1) p += __shfl_xor_sync(0xffffffffu, p, o);
            __shared__ float smb[4];
            if ((t & 31) == 0) smb[t >> 5] = p;
            __syncwarp();
            asm volatile("bar.sync 1, 128;");
            float s2 = smb[0] + smb[1] + smb[2] + smb[3];
            float bn = fmaxf(sqrtf(s2), MINN);
            float z  = SQC * bn;
            g_bh[t] = tanhf(z) / z * v;
        }
        return;
    }

    const float* xr = x + (size_t)row * 4096;

    float p = 0.0f;
    #pragma unroll
    for (int k = 0; k < 16; k++) { float v = xr[t + (k << 8)]; p += v * v; }
    #pragma unroll
    for (int o = 16; o > 0; o >>= 1) p += __shfl_xor_sync(0xffffffffu, p, o);
    __shared__ float sm[8];
    __shared__ float s_scale;
    if ((t & 31) == 0) sm[t >> 5] = p;
    __syncthreads();
    if (t == 0) {
        float s2 = 0.0f;
        #pragma unroll
        for (int i = 0; i < 8; i++) s2 += sm[i];
        float yn = fmaxf(sqrtf(s2), MINN);
        float z  = SQC * yn;
        s_scale  = artanhc(z) / z;
    }
    __syncthreads();
    float sc = s_scale;

    float* ur = g_u + (size_t)row * TSZ;
    for (int idx = t; idx < TSZ; idx += 256) {
        int r = idx / TW, c = idx - r * TW;
        float v = 0.0f;
        if (r >= 1 && r <= 64 && c >= 1 && c <= 64)
            v = xr[(r - 1) * 64 + (c - 1)] * sc;
        ur[idx] = v;
    }
}

// ---------------------------------------------------------------------------
// Mobius scan scalar math — short chain (no sqrt on common path).
// acc = P*q;  qv = <q,v>.  Returns (sA, sBt); updates a2 = |acc'|^2.
// ---------------------------------------------------------------------------
__device__ __forceinline__ float2 step_scalars(float sv2, float qv, float P, float& a2) {
    float z2 = CC * sv2;                           // z^2
    float tau;
    if (z2 < 0.0625f) {                            // z < 0.25 (always, this data)
        tau = 1.0f + z2 * (-0.33333334f + z2 * (0.13333334f - z2 * 0.053968254f));
    } else {
        float vn = sv2 * frsq(fmaxf(sv2, 1e-28f));
        float z  = SQC * vn;
        float t  = fexp2(z * 2.8853901f);          // e^{2z}
        tau = (t - 1.0f) * frcp((t + 1.0f) * z);
    }
    float tn2 = tau * tau * sv2;                   // |t|^2 before project
    float ts  = tau;
    if (tn2 > MAXN2) ts = tau * (MAXN * frsq(tn2));  // project(t), rare
    float y2  = ts * ts * sv2;
    float xy  = ts * (P * qv);
    float x2  = a2;
    float A   = 1.0f + 2.0f * CC * xy + CC * y2;
    float B   = 1.0f - CC * x2;
    float den = fmaxf(1.0f + 2.0f * CC * xy + CC * CC * x2 * y2, MINN);
    float inv = frcp(den);
    float n2  = (A * A * x2 + 2.0f * A * B * xy + B * B * y2) * (inv * inv);
    float ps  = 1.0f;
    if (n2 > MAXN2) ps = MAXN * frsq(fmaxf(n2, 1e-28f));  // project(acc'), rare
    a2 = ps * ps * n2;
    return make_float2(A * inv * ps, B * inv * ps * ts);
}

__device__ __forceinline__ float2 final_scalars(float sacc, float a2, float bh) {
    float y2  = 4096.0f * bh * bh;
    float xy  = bh * sacc;
    float x2  = a2;
    float A   = 1.0f + 2.0f * CC * xy + CC * y2;
    float B   = 1.0f - CC * x2;
    float den = fmaxf(1.0f + 2.0f * CC * xy + CC * CC * x2 * y2, MINN);
    float inv = frcp(den);
    float n2  = (A * A * x2 + 2.0f * A * B * xy + B * B * y2) * (inv * inv);
    float ps  = 1.0f;
    if (n2 > MAXN2) ps = MAXN * frsq(fmaxf(n2, 1e-28f));
    return make_float2(A * inv * ps, B * inv * ps * bh);
}

// load one 6-wide window row (16B-aligned) as 5 overlapping f32x2 pairs
__device__ __forceinline__ void loadrow(const float* p, u64* row) {
    float4 a = *(const float4*)p;           // floats 0-3 (LDS.128)
    float2 b = *(const float2*)(p + 4);     // floats 4-5 (LDS.64)
    row[0] = pk(a.x, a.y);
    row[1] = pk(a.y, a.z);
    row[2] = pk(a.z, a.w);
    row[3] = pk(a.w, b.x);
    row[4] = pk(b.x, b.y);
}

// ---------------------------------------------------------------------------
// Kernel 2: one CTA per (b, channel pair) — exact R11 structure (best: 785us)
// with ONE change: row-streaming conv (one 5-pair row live instead of a
// 3-row rolling window) to cut ~20 live registers and give ptxas room to
// overlap the post-barrier scalar chain with the next iteration's conv.
// ---------------------------------------------------------------------------
__global__ __launch_bounds__(256, 2)
void main_kernel(const float* __restrict__ w, float* __restrict__ out) {
    const int b    = blockIdx.y;
    const int c0   = blockIdx.x * 2;
    const int tid  = threadIdx.x;
    const int ty   = tid >> 4;
    const int tx   = tid & 15;
    const int lane = tid & 31;
    const int wid  = tid >> 5;
    const int par  = lane & 1;          // my scalar-chain channel (0 or 1)

    __shared__ float  su[2 * TSZ];      // double-buffered 66x68 tile
    __shared__ u64    swp[2][576];      // weights pre-duplicated (w,w)
    __shared__ float2 sred[2][16];      // [buf][wid*2 + parity]

    for (int i = tid; i < 1152; i += 256) {
        int cc = i / 576, rem = i - cc * 576;
        float wv = w[(size_t)(c0 + cc) * 576 + rem];
        swp[cc][rem] = pk(wv, wv);
    }

    const unsigned su_s = (unsigned)__cvta_generic_to_shared(su);
    const float4* gbase = (const float4*)(g_u + (size_t)(b * 64) * TSZ);
    const int tail = tid + 1024;            // only first 98 threads copy chunk 5

    // preload tile 0 into buf0 via cp.async
    #pragma unroll
    for (int k = 0; k < 4; k++) {
        int i = tid + (k << 8);
        cpasync16(su_s + i * 16, gbase + i);
    }
    if (tail < TSZ4) cpasync16(su_s + tail * 16, gbase + tail);
    CP_COMMIT();
    CP_WAIT0();
    __syncthreads();

    u64 q0a[8], q1a[8];                 // acc = P * q, packed col pairs
    #pragma unroll
    for (int i = 0; i < 8; i++) { q0a[i] = 0ull; q1a[i] = 0ull; }
    float a2m = 0.0f, Pm = 1.0f;        // per-lane: channel `par`'s scan state

    const int baseoff = (4 * ty) * TW + 4 * tx;

    #pragma unroll 2
    for (int j = 0; j < 64; j++) {
        const int cur = j & 1;

        // ---- branchless async prefetch of tile (j+1)&63 into other buffer ----
        {
            const float4* gn = gbase + (size_t)((j + 1) & 63) * TSZ4;
            unsigned sn = su_s + (cur ^ 1) * (TSZ * 4);
            #pragma unroll
            for (int k = 0; k < 4; k++) {
                int i = tid + (k << 8);
                cpasync16(sn + i * 16, gn + i);
            }
            if (tail < TSZ4) cpasync16(sn + tail * 16, gn + tail);
            CP_COMMIT();
        }

        const float* basep = su + cur * TSZ + baseoff;
        const u64* wp0 = &swp[0][j * 9];
        const u64* wp1 = &swp[1][j * 9];

        // ---- conv: row-streaming — ONE input row (5 packed pairs) live ----
        u64 v0[8], v1[8];
        #pragma unroll
        for (int i = 0; i < 8; i++) { v0[i] = 0ull; v1[i] = 0ull; }

        #pragma unroll
        for (int dr = 0; dr < 6; dr++) {
            u64 row[5];
            loadrow(basep + dr * TW, row);
            const int orlo = (dr - 2 > 0) ? dr - 2 : 0;
            const int orhi = (dr < 3) ? dr : 3;
            #pragma unroll
            for (int orow = orlo; orow <= orhi; orow++) {
                const int r = dr - orow;
                #pragma unroll
                for (int k = 0; k < 3; k++) {
                    u64 wa = wp0[r * 3 + k];
                    u64 wb = wp1[r * 3 + k];
                    v0[orow * 2]     = fma2(row[k],     wa, v0[orow * 2]);
                    v0[orow * 2 + 1] = fma2(row[2 + k], wa, v0[orow * 2 + 1]);
                    v1[orow * 2]     = fma2(row[k],     wb, v1[orow * 2]);
                    v1[orow * 2 + 1] = fma2(row[2 + k], wb, v1[orow * 2 + 1]);
                }
            }
        }

        // ---- fused packed reduction: |v|^2 and <q,v> per channel ----
        u64 sq0 = 0ull, av0 = 0ull, sq1 = 0ull, av1 = 0ull;
        #pragma unroll
        for (int i = 0; i < 8; i++) {
            sq0 = fma2(v0[i], v0[i], sq0);
            av0 = fma2(q0a[i], v0[i], av0);
            sq1 = fma2(v1[i], v1[i], sq1);
            av1 = fma2(q1a[i], v1[i], av1);
        }
        float2 pa = unpk(sq0), pb = unpk(av0), pc = unpk(sq1), pd = unpk(av1);
        float s0p = pa.x + pa.y, d0p = pb.x + pb.y;   // ch0 partials
        float s1p = pc.x + pc.y, d1p = pd.x + pd.y;   // ch1 partials

        // ---- parity-split butterfly: even lanes own ch0, odd lanes ch1 ----
        float s_mine = par ? s1p : s0p;
        float d_mine = par ? d1p : d0p;
        float s_oth  = par ? s0p : s1p;
        float d_oth  = par ? d0p : d1p;
        s_mine += __shfl_xor_sync(0xffffffffu, s_oth, 1);
        d_mine += __shfl_xor_sync(0xffffffffu, d_oth, 1);
        #pragma unroll
        for (int o = 2; o <= 16; o <<= 1) {
            s_mine += __shfl_xor_sync(0xffffffffu, s_mine, o);
            d_mine += __shfl_xor_sync(0xffffffffu, d_mine, o);
        }
        if (lane < 2) sred[cur][wid * 2 + par] = make_float2(s_mine, d_mine);

        // prefetch must land before the barrier publishes the buffer
        CP_WAIT0();
        __syncthreads();                      // single barrier per scan step

        // tree-sum the 8 warp partials of MY parity (float2, broadcast reads)
        float2 r0 = sred[cur][0 * 2 + par], r1 = sred[cur][1 * 2 + par];
        float2 r2 = sred[cur][2 * 2 + par], r3 = sred[cur][3 * 2 + par];
        float2 r4 = sred[cur][4 * 2 + par], r5 = sred[cur][5 * 2 + par];
        float2 r6 = sred[cur][6 * 2 + par], r7 = sred[cur][7 * 2 + par];
        float sv2 = ((r0.x + r1.x) + (r2.x + r3.x)) + ((r4.x + r5.x) + (r6.x + r7.x));
        float qv  = ((r0.y + r1.y) + (r2.y + r3.y)) + ((r4.y + r5.y) + (r6.y + r7.y));

        // ---- lane-parity scalar chain ----
        float2 s = step_scalars(sv2, qv, Pm, a2m);
        Pm *= s.x;
        float qcm = s.y * frcp(Pm);
        float qc0 = __shfl_sync(0xffffffffu, qcm, 0);
        float qc1 = __shfl_sync(0xffffffffu, qcm, 1);
        u64 QC0 = pk(qc0, qc0), QC1 = pk(qc1, qc1);
        #pragma unroll
        for (int i = 0; i < 8; i++) {
            q0a[i] = fma2(QC0, v0[i], q0a[i]);
            q1a[i] = fma2(QC1, v1[i], q1a[i]);
        }
    }

    // ---- epilogue: mobius bias add + project (acc = P*q) ----
    float sa0 = 0.0f, sa1 = 0.0f;
    #pragma unroll
    for (int i = 0; i < 8; i++) {
        float2 p0 = unpk(q0a[i]); sa0 += p0.x + p0.y;
        float2 p1 = unpk(q1a[i]); sa1 += p1.x + p1.y;
    }
    {
        float m  = par ? sa1 : sa0;
        float ot = par ? sa0 : sa1;
        m += __shfl_xor_sync(0xffffffffu, ot, 1);
        #pragma unroll
        for (int o = 2; o <= 16; o <<= 1)
            m += __shfl_xor_sync(0xffffffffu, m, o);
        if (lane < 2) sred[0][wid * 2 + par] = make_float2(m, 0.f);
    }
    __syncthreads();
    float tm = 0.0f;
    #pragma unroll
    for (int i = 0; i < 8; i++) tm += sred[0][i * 2 + par].x;

    // lane-parity final scalars, then broadcast
    float2 f = final_scalars(Pm * tm, a2m, g_bh[c0 + par]);
    float fxm = f.x * Pm;
    float fa0 = __shfl_sync(0xffffffffu, fxm, 0);
    float fb0 = __shfl_sync(0xffffffffu, f.y, 0);
    float fa1 = __shfl_sync(0xffffffffu, fxm, 1);
    float fb1 = __shfl_sync(0xffffffffu, f.y, 1);
    u64 FA0 = pk(fa0, fa0), FB0 = pk(fb0, fb0);
    u64 FA1 = pk(fa1, fa1), FB1 = pk(fb1, fb1);

    u64* o0 = (u64*)(out + ((size_t)(b * 128 + c0)) * 4096);
    u64* o1 = o0 + 2048;
    #pragma unroll
    for (int orow = 0; orow < 4; orow++) {
        #pragma unroll
        for (int p = 0; p < 2; p++) {
            int pos = (4 * ty + orow) * 32 + 2 * tx + p;   // in float2 units
            o0[pos] = fma2(FA0, q0a[orow * 2 + p], FB0);
            o1[pos] = fma2(FA1, q1a[orow * 2 + p], FB1);
        }
    }
}

// ---------------------------------------------------------------------------
extern "C" void kernel_launch(void* const* d_in, const int* in_sizes, int n_in,
                              void* d_out, int out_size) {
    const float* x    = (const float*)d_in[0];   // [32,64,64,64]
    const float* wgt  = (const float*)d_in[1];   // [128,64,3,3]
    const float* bias = (const float*)d_in[2];   // [128]
    float* out = (float*)d_out;                  // [32,128,64,64]

    u_kernel<<<2049, 256>>>(x, bias);            // block 2048 also does bias
    dim3 grid(64, 32);                           // (cout/2, bs)
    main_kernel<<<grid, 256>>>(wgt, out);
}